// round 1
// baseline (speedup 1.0000x reference)
#include <cuda_runtime.h>
#include <cuda_bf16.h>

#define N_NODES 100000
#define N_EDGES 1600000
#define F0 69
#define F1 128
#define F2 64
#define NUM_GRAPHS 128
#define SCAN_NBLK ((N_NODES + 1023) / 1024)   // 98
#define NB 16                                  // nodes per GEMM tile
#define N_TILES (N_NODES / NB)                 // 6250 (exact)

// ---------------- scratch (static device globals; no runtime alloc) -------
__device__ int   g_deg_out[N_NODES];
__device__ int   g_deg_in[N_NODES];
__device__ float g_inv_out[N_NODES];
__device__ float g_inv_in[N_NODES];
__device__ int   g_row_ptr[N_NODES + 1];
__device__ int   g_cursor[N_NODES];
__device__ int   g_block_sums[128];
__device__ int   g_csr_src[N_EDGES];
__device__ float g_agg1[N_NODES * F0];   // normalized layer-1 aggregate
__device__ float g_h1n[N_NODES * F1];    // relu(agg1@W1) * inv_out
__device__ float g_g2[N_NODES * F2];     // h1n @ W2
// --------------------------------------------------------------------------

__global__ void k_init(float* __restrict__ out) {
    int i = blockIdx.x * blockDim.x + threadIdx.x;
    int stride = gridDim.x * blockDim.x;
    for (int j = i; j < N_NODES; j += stride) {
        g_deg_out[j] = 0;
        g_deg_in[j]  = 0;
        g_cursor[j]  = 0;
    }
    for (int j = i; j < NUM_GRAPHS * F2; j += stride) out[j] = 0.0f;
}

__global__ void k_deg(const int* __restrict__ src, const int* __restrict__ dst) {
    int e = blockIdx.x * blockDim.x + threadIdx.x;
    if (e < N_EDGES) {
        atomicAdd(&g_deg_out[src[e]], 1);
        atomicAdd(&g_deg_in[dst[e]], 1);
    }
}

__global__ void k_inv() {
    int i = blockIdx.x * blockDim.x + threadIdx.x;
    if (i < N_NODES) {
        g_inv_out[i] = rsqrtf(fmaxf((float)g_deg_out[i], 1.0f));
        g_inv_in[i]  = rsqrtf(fmaxf((float)g_deg_in[i], 1.0f));
    }
}

// ---- 3-kernel exclusive scan of g_deg_in into g_row_ptr ------------------
__global__ void k_scan_local() {
    __shared__ int sh[1024];
    int t = threadIdx.x;
    int i = blockIdx.x * 1024 + t;
    int v = (i < N_NODES) ? g_deg_in[i] : 0;
    sh[t] = v;
    __syncthreads();
    for (int off = 1; off < 1024; off <<= 1) {
        int tmp = (t >= off) ? sh[t - off] : 0;
        __syncthreads();
        sh[t] += tmp;
        __syncthreads();
    }
    if (i < N_NODES) g_row_ptr[i] = sh[t] - v;       // block-local exclusive
    if (t == 1023) g_block_sums[blockIdx.x] = sh[t]; // block total
}

__global__ void k_scan_partials() {
    __shared__ int sh[128];
    int t = threadIdx.x;
    int v = (t < SCAN_NBLK) ? g_block_sums[t] : 0;
    sh[t] = v;
    __syncthreads();
    for (int off = 1; off < 128; off <<= 1) {
        int tmp = (t >= off) ? sh[t - off] : 0;
        __syncthreads();
        sh[t] += tmp;
        __syncthreads();
    }
    if (t < SCAN_NBLK) g_block_sums[t] = sh[t] - v;  // exclusive
}

__global__ void k_scan_add() {
    int i = blockIdx.x * 1024 + threadIdx.x;
    if (i < N_NODES) g_row_ptr[i] += g_block_sums[i >> 10];
    if (i == 0) g_row_ptr[N_NODES] = N_EDGES;
}

__global__ void k_fill(const int* __restrict__ src, const int* __restrict__ dst) {
    int e = blockIdx.x * blockDim.x + threadIdx.x;
    if (e < N_EDGES) {
        int d = dst[e];
        int pos = g_row_ptr[d] + atomicAdd(&g_cursor[d], 1);
        g_csr_src[pos] = src[e];
    }
}

// ---- SpMM layer 1: agg1[i] = inv_in[i] * sum_{e->i} x[s]*inv_out[s] ------
__global__ void k_spmm1(const float* __restrict__ x) {
    int i = blockIdx.x * 8 + (threadIdx.x >> 5);
    if (i >= N_NODES) return;
    int lane = threadIdx.x & 31;
    int beg = g_row_ptr[i], end = g_row_ptr[i + 1];
    float a0 = 0.f, a1 = 0.f, a2 = 0.f;
    int e = beg;
    for (; e + 1 < end; e += 2) {
        int s0 = g_csr_src[e];
        int s1 = g_csr_src[e + 1];
        float w0 = g_inv_out[s0];
        float w1 = g_inv_out[s1];
        const float* p0 = x + (size_t)s0 * F0;
        const float* p1 = x + (size_t)s1 * F0;
        a0 += p0[lane] * w0 + p1[lane] * w1;
        a1 += p0[lane + 32] * w0 + p1[lane + 32] * w1;
        if (lane < F0 - 64) a2 += p0[lane + 64] * w0 + p1[lane + 64] * w1;
    }
    if (e < end) {
        int s0 = g_csr_src[e];
        float w0 = g_inv_out[s0];
        const float* p0 = x + (size_t)s0 * F0;
        a0 += p0[lane] * w0;
        a1 += p0[lane + 32] * w0;
        if (lane < F0 - 64) a2 += p0[lane + 64] * w0;
    }
    float sc = g_inv_in[i];
    float* o = g_agg1 + (size_t)i * F0;
    o[lane] = a0 * sc;
    o[lane + 32] = a1 * sc;
    if (lane < F0 - 64) o[lane + 64] = a2 * sc;
}

// ---- GEMM1: h1n = relu(agg1 @ W1) * inv_out  (per-node rows) -------------
__global__ void __launch_bounds__(128) k_gemm1(const float* __restrict__ W1) {
    __shared__ float W1s[F0 * F1];     // 35328 B
    __shared__ float a_s[NB * F0];     // 4416 B
    int tid = threadIdx.x;
    for (int idx = tid; idx < F0 * F1; idx += 128) W1s[idx] = W1[idx];
    __syncthreads();
    int tj = tid & 31;
    int tn = tid >> 5;
    for (int tile = blockIdx.x; tile < N_TILES; tile += gridDim.x) {
        int i0 = tile * NB;
        for (int idx = tid; idx < NB * F0; idx += 128)
            a_s[idx] = g_agg1[(size_t)i0 * F0 + idx];
        __syncthreads();
        float acc[4][4];
#pragma unroll
        for (int m = 0; m < 4; m++)
#pragma unroll
            for (int mm = 0; mm < 4; mm++) acc[m][mm] = 0.f;
#pragma unroll 3
        for (int k = 0; k < F0; k++) {
            float w0 = W1s[k * F1 + tj];
            float w1 = W1s[k * F1 + tj + 32];
            float w2 = W1s[k * F1 + tj + 64];
            float w3 = W1s[k * F1 + tj + 96];
            float b0 = a_s[tn * F0 + k];
            float b1 = a_s[(tn + 4) * F0 + k];
            float b2 = a_s[(tn + 8) * F0 + k];
            float b3 = a_s[(tn + 12) * F0 + k];
            acc[0][0] += b0 * w0; acc[1][0] += b0 * w1; acc[2][0] += b0 * w2; acc[3][0] += b0 * w3;
            acc[0][1] += b1 * w0; acc[1][1] += b1 * w1; acc[2][1] += b1 * w2; acc[3][1] += b1 * w3;
            acc[0][2] += b2 * w0; acc[1][2] += b2 * w1; acc[2][2] += b2 * w2; acc[3][2] += b2 * w3;
            acc[0][3] += b3 * w0; acc[1][3] += b3 * w1; acc[2][3] += b3 * w2; acc[3][3] += b3 * w3;
        }
#pragma unroll
        for (int mm = 0; mm < 4; mm++) {
            int i = i0 + tn + 4 * mm;
            float sc = g_inv_out[i];
            float* o = g_h1n + (size_t)i * F1;
#pragma unroll
            for (int m = 0; m < 4; m++) {
                float v = acc[m][mm];
                v = v > 0.f ? v : 0.f;
                o[tj + 32 * m] = v * sc;
            }
        }
        __syncthreads();
    }
}

// ---- GEMM2: g2 = h1n @ W2 ------------------------------------------------
__global__ void __launch_bounds__(128) k_gemm2(const float* __restrict__ W2) {
    __shared__ float W2s[F1 * F2];     // 32768 B
    __shared__ float t_s[NB * F1];     // 8192 B
    int tid = threadIdx.x;
    for (int idx = tid; idx < F1 * F2; idx += 128) W2s[idx] = W2[idx];
    __syncthreads();
    int tc = tid & 31;
    int tn = tid >> 5;
    for (int tile = blockIdx.x; tile < N_TILES; tile += gridDim.x) {
        int i0 = tile * NB;
        for (int idx = tid; idx < NB * F1; idx += 128)
            t_s[idx] = g_h1n[(size_t)i0 * F1 + idx];
        __syncthreads();
        float acc[2][4];
#pragma unroll
        for (int m = 0; m < 2; m++)
#pragma unroll
            for (int mm = 0; mm < 4; mm++) acc[m][mm] = 0.f;
#pragma unroll 4
        for (int j = 0; j < F1; j++) {
            float w0 = W2s[j * F2 + tc];
            float w1 = W2s[j * F2 + tc + 32];
#pragma unroll
            for (int mm = 0; mm < 4; mm++) {
                float tv = t_s[(tn + 4 * mm) * F1 + j];
                acc[0][mm] += tv * w0;
                acc[1][mm] += tv * w1;
            }
        }
#pragma unroll
        for (int mm = 0; mm < 4; mm++) {
            int i = i0 + tn + 4 * mm;
            float* o = g_g2 + (size_t)i * F2;
            o[tc] = acc[0][mm];
            o[tc + 32] = acc[1][mm];
        }
        __syncthreads();
    }
}

// ---- SpMM layer 2 + relu + fused per-graph max readout -------------------
__global__ void k_spmm2(const int* __restrict__ graph_ids, float* __restrict__ out) {
    int i = blockIdx.x * 8 + (threadIdx.x >> 5);
    if (i >= N_NODES) return;
    int lane = threadIdx.x & 31;
    int beg = g_row_ptr[i], end = g_row_ptr[i + 1];
    float a0 = 0.f, a1 = 0.f;
    int e = beg;
    for (; e + 1 < end; e += 2) {
        int s0 = g_csr_src[e];
        int s1 = g_csr_src[e + 1];
        const float* p0 = g_g2 + (size_t)s0 * F2;
        const float* p1 = g_g2 + (size_t)s1 * F2;
        a0 += p0[lane] + p1[lane];
        a1 += p0[lane + 32] + p1[lane + 32];
    }
    if (e < end) {
        const float* p0 = g_g2 + (size_t)g_csr_src[e] * F2;
        a0 += p0[lane];
        a1 += p0[lane + 32];
    }
    float sc = g_inv_in[i];
    float v0 = fmaxf(a0 * sc, 0.0f);
    float v1 = fmaxf(a1 * sc, 0.0f);
    int g = graph_ids[i];
    int* ob = (int*)out + g * F2;
    // non-negative floats: int compare == float compare; out pre-zeroed
    atomicMax(ob + lane, __float_as_int(v0));
    atomicMax(ob + lane + 32, __float_as_int(v1));
}

extern "C" void kernel_launch(void* const* d_in, const int* in_sizes, int n_in,
                              void* d_out, int out_size) {
    const float* x   = (const float*)d_in[0];
    const float* W1  = (const float*)d_in[1];
    const float* W2  = (const float*)d_in[2];
    const int*   src = (const int*)d_in[3];
    const int*   dst = (const int*)d_in[4];
    const int*   gid = (const int*)d_in[5];
    float* out = (float*)d_out;

    k_init<<<256, 256>>>(out);
    k_deg<<<(N_EDGES + 255) / 256, 256>>>(src, dst);
    k_inv<<<(N_NODES + 255) / 256, 256>>>();
    k_scan_local<<<SCAN_NBLK, 1024>>>();
    k_scan_partials<<<1, 128>>>();
    k_scan_add<<<SCAN_NBLK, 1024>>>();
    k_fill<<<(N_EDGES + 255) / 256, 256>>>(src, dst);
    k_spmm1<<<(N_NODES + 7) / 8, 256>>>(x);
    k_gemm1<<<592, 128>>>(W1);
    k_gemm2<<<592, 128>>>(W2);
    k_spmm2<<<(N_NODES + 7) / 8, 256>>>(gid, out);
}